// round 8
// baseline (speedup 1.0000x reference)
#include <cuda_runtime.h>
#include <cuda_bf16.h>
#include <cstdint>

// MaxUnpool2D, scatter-shaped, persistent single-wave kernel.
// One resident wave (148 SMs x 8 blocks x 256 threads) grid-strides over the
// pooled tensor; each iteration handles one pooled float4 group: 2 coalesced
// loads + 4 coalesced float4 stores (the full private 2x2 output window).
// Loop unrolled x2 so two iterations' loads overlap.
// Argmax indices are unique per pooled cell -> every output element written
// exactly once; no atomics, no zero-init pass.
//
// x:    [B=8, H=128, W=128, C=64] float32
// mask: [B, H, W, C] int32 (flat idx into [HOUT*WOUT*C] per batch)
// out:  [B, 256, 256, C] float32

static constexpr int Bc   = 8;
static constexpr int Hc   = 128;
static constexpr int Wc   = 128;
static constexpr int Cc   = 64;
static constexpr int HOUT = 256;
static constexpr int WOUT = 256;
static constexpr int C4   = Cc / 4;                  // 16
static constexpr int N4   = Bc * Hc * Wc * C4;       // 2,097,152 pooled groups

static constexpr int BLOCKS  = 148 * 8;              // one full resident wave
static constexpr int THREADS = 256;

__device__ __forceinline__ void do_group(
    int g,
    const float4* __restrict__ x4,
    const int4*   __restrict__ m4,
    float4*       __restrict__ out4,
    const int4& m, const float4& v)
{
    // g -> (b, h, w, c4), all pow2
    int c4 = g & (C4 - 1);
    int t  = g >> 4;
    int w  = t & (Wc - 1);
    t >>= 7;
    int h  = t & (Hc - 1);
    int b  = t >> 7;

    int c  = c4 << 2;
    int ho = h << 1;
    int wo = w << 1;

    int obase = ((b * HOUT + ho) * WOUT + wo) * C4 + c4;

#pragma unroll
    for (int dh = 0; dh < 2; ++dh) {
#pragma unroll
        for (int dw = 0; dw < 2; ++dw) {
            int flat = (((ho + dh) * WOUT) + (wo + dw)) * Cc + c;
            float4 o;
            o.x = (m.x == flat    ) ? v.x : 0.0f;
            o.y = (m.y == flat + 1) ? v.y : 0.0f;
            o.z = (m.z == flat + 2) ? v.z : 0.0f;
            o.w = (m.w == flat + 3) ? v.w : 0.0f;
            __stcs(&out4[obase + dh * (WOUT * C4) + dw * C4], o);
        }
    }
}

__global__ __launch_bounds__(THREADS, 8) void max_unpool_persist(
    const float4* __restrict__ x4,
    const int4*   __restrict__ m4,
    float4*       __restrict__ out4)
{
    const int stride = BLOCKS * THREADS;             // 303,104
    int g = blockIdx.x * THREADS + threadIdx.x;

    // Main unrolled-x2 loop: both iterations' loads issued before either's
    // stores, doubling loads in flight.
    for (; g + stride < N4; g += 2 * stride) {
        int g1 = g + stride;
        int4   m0 = __ldcs(&m4[g]);
        float4 v0 = __ldcs(&x4[g]);
        int4   m1 = __ldcs(&m4[g1]);
        float4 v1 = __ldcs(&x4[g1]);
        do_group(g,  x4, m4, out4, m0, v0);
        do_group(g1, x4, m4, out4, m1, v1);
    }
    if (g < N4) {
        int4   m = __ldcs(&m4[g]);
        float4 v = __ldcs(&x4[g]);
        do_group(g, x4, m4, out4, m, v);
    }
}

extern "C" void kernel_launch(void* const* d_in, const int* in_sizes, int n_in,
                              void* d_out, int out_size)
{
    const float4* x4 = (const float4*)d_in[0];   // input_pool float32
    const int4*   m4 = (const int4*)  d_in[1];   // pool_mask int32
    float4*       o4 = (float4*)d_out;

    max_unpool_persist<<<BLOCKS, THREADS>>>(x4, m4, o4);
}

// round 9
// speedup vs baseline: 1.1044x; 1.1044x over previous
#include <cuda_runtime.h>
#include <cuda_bf16.h>
#include <cstdint>

// MaxUnpool2D, scatter-shaped (best round-2 shape), with WRITE-THROUGH stores.
// One thread per pooled float4 group: 2 coalesced loads + 4 coalesced float4
// stores covering the cell's private 2x2 output window. Argmax indices are
// unique per pooled cell -> every output element written exactly once; no
// atomics, no zero-init pass.
//
// Change vs best kernel: __stcs -> __stwt. Output (128 MB) ~= L2 capacity
// (126 MB); evict-first streaming stores leave the writeback trailing the
// kernel (ncu 28.6us vs bench 35.5us). Write-through drains lines to DRAM
// while the kernel runs, overlapping writeback with the read streams.
//
// x:    [B=8, H=128, W=128, C=64] float32
// mask: [B, H, W, C] int32 (flat idx into [HOUT*WOUT*C] per batch)
// out:  [B, 256, 256, C] float32

static constexpr int Bc   = 8;
static constexpr int Hc   = 128;
static constexpr int Wc   = 128;
static constexpr int Cc   = 64;
static constexpr int HOUT = 256;
static constexpr int WOUT = 256;
static constexpr int C4   = Cc / 4;             // 16
static constexpr int N4   = Bc * Hc * Wc * C4;  // 2,097,152 pooled float4 groups

__global__ __launch_bounds__(256) void max_unpool_scatter_wt(
    const float4* __restrict__ x4,
    const int4*   __restrict__ m4,
    float4*       __restrict__ out4)
{
    int idx = blockIdx.x * blockDim.x + threadIdx.x;
    if (idx >= N4) return;

    // idx -> (b, h, w, c4), all pow2
    int c4 = idx & (C4 - 1);
    int t  = idx >> 4;
    int w  = t & (Wc - 1);
    t >>= 7;
    int h  = t & (Hc - 1);
    int b  = t >> 7;

    int4   m = __ldcs(&m4[idx]);
    float4 v = __ldcs(&x4[idx]);

    int c  = c4 << 2;
    int ho = h << 1;
    int wo = w << 1;

    // output float4 offset base: ((b*HOUT + ho)*WOUT + wo)*C4 + c4
    int obase = ((b * HOUT + ho) * WOUT + wo) * C4 + c4;

#pragma unroll
    for (int dh = 0; dh < 2; ++dh) {
#pragma unroll
        for (int dw = 0; dw < 2; ++dw) {
            int flat = (((ho + dh) * WOUT) + (wo + dw)) * Cc + c;
            float4 o;
            o.x = (m.x == flat    ) ? v.x : 0.0f;
            o.y = (m.y == flat + 1) ? v.y : 0.0f;
            o.z = (m.z == flat + 2) ? v.z : 0.0f;
            o.w = (m.w == flat + 3) ? v.w : 0.0f;
            __stwt(&out4[obase + dh * (WOUT * C4) + dw * C4], o);
        }
    }
}

extern "C" void kernel_launch(void* const* d_in, const int* in_sizes, int n_in,
                              void* d_out, int out_size)
{
    const float4* x4 = (const float4*)d_in[0];   // input_pool float32
    const int4*   m4 = (const int4*)  d_in[1];   // pool_mask int32
    float4*       o4 = (float4*)d_out;

    int threads = 256;
    int blocks  = (N4 + threads - 1) / threads;  // 8192
    max_unpool_scatter_wt<<<blocks, threads>>>(x4, m4, o4);
}